// round 5
// baseline (speedup 1.0000x reference)
#include <cuda_runtime.h>

#define BATCH 2
#define NPTS  4096
#define NTOT  (BATCH*NPTS)

#define LOG2E_F 1.4426950408889634f
#define LN2_F   0.6931471805599453f
#define LOGW_F  (-8.317766166719343f)   /* -ln(4096), uniform weights both sides */

// Packed point data: (x, y, z, 0.5*|p|^2)
__device__ float4 g_PX[NTOT];   // true_data  (x side)
__device__ float4 g_PY[NTOT];   // particles  (y side)
// Dual potentials, double-buffered. Index 2: [buffer][which][B*N]
// which: 0 = a_y (rows over y), 1 = b_x (rows over x), 2 = a_x, 3 = b_y
__device__ float  g_dual[2][4][NTOT];

__device__ __forceinline__ float ex2f(float x){ float r; asm("ex2.approx.ftz.f32 %0, %1;" : "=f"(r) : "f"(x)); return r; }
__device__ __forceinline__ float lg2f(float x){ float r; asm("lg2.approx.f32 %0, %1;"     : "=f"(r) : "f"(x)); return r; }

__global__ void pack_kernel(const float* __restrict__ x, const float* __restrict__ y){
    int i = blockIdx.x*blockDim.x + threadIdx.x;
    if (i < NTOT){
        float a = x[3*i+0], b = x[3*i+1], c = x[3*i+2];
        g_PX[i] = make_float4(a, b, c, 0.5f*(a*a + b*b + c*c));
        a = y[3*i+0]; b = y[3*i+1]; c = y[3*i+2];
        g_PY[i] = make_float4(a, b, c, 0.5f*(a*a + b*b + c*c));
    }
}

// One launch = one annealing stage: 4 softmin tasks x 2 batches x 512 row-blocks.
// task 0: a_y' = softmin(eps, C_yx, a_log + b_x/eps)   P=y, Q=x, dual=b_x
// task 1: b_x' = softmin(eps, C_xy, b_log + a_y/eps)   P=x, Q=y, dual=a_y
// task 2: a_x' = softmin(eps, C_xx, a_log + a_x/eps)   P=x, Q=x, dual=a_x
// task 3: b_y' = softmin(eps, C_yy, b_log + b_y/eps)   P=y, Q=y, dual=b_y
// mode 0: init (no dual term, plain store); mode 1: 0.5*(old+new); mode 2: plain store.
__global__ __launch_bounds__(256, 2)
void softmin_kernel(float eps, int src, int dst, int mode)
{
    const int tid    = threadIdx.x;
    const int rowblk = blockIdx.x & 511;     // 512 row-blocks of 8 rows
    const int combo  = blockIdx.x >> 9;      // 0..7
    const int task   = combo >> 1;
    const int batch  = combo & 1;
    const int base   = batch * NPTS;

    const float inv = 1.0f / eps;
    const float s2  = inv * LOG2E_F;         // scale into log2 domain

    const float4* P; const float4* Q; const float* dualin; float* outp; const float* oldp;
    if      (task == 0){ P=g_PY+base; Q=g_PX+base; dualin=g_dual[src][1]+base; outp=g_dual[dst][0]+base; oldp=g_dual[src][0]+base; }
    else if (task == 1){ P=g_PX+base; Q=g_PY+base; dualin=g_dual[src][0]+base; outp=g_dual[dst][1]+base; oldp=g_dual[src][1]+base; }
    else if (task == 2){ P=g_PX+base; Q=g_PX+base; dualin=g_dual[src][2]+base; outp=g_dual[dst][2]+base; oldp=g_dual[src][2]+base; }
    else               { P=g_PY+base; Q=g_PY+base; dualin=g_dual[src][3]+base; outp=g_dual[dst][3]+base; oldp=g_dual[src][3]+base; }

    const int row0 = rowblk * 8;

    // Per-row constants (replicated across all threads). Row constant
    // (logw - 0.5|p|^2/eps) is pulled OUT of the logsumexp -> not in inner loop.
    float px[8], py[8], pz[8];
#pragma unroll
    for (int r = 0; r < 8; r++){
        float4 p = P[row0 + r];
        px[r] = p.x * s2;  py[r] = p.y * s2;  pz[r] = p.z * s2;
    }

    // ---- pass 1: row maxima of v = tj + (p.q)/eps*log2e ----
    float m[8];
#pragma unroll
    for (int r = 0; r < 8; r++) m[r] = -3.0e38f;

    for (int j = tid; j < NPTS; j += 256){
        float4 q = Q[j];                                    // q.w = 0.5|q|^2
        float tj = (mode == 0) ? (-q.w * s2) : ((dualin[j] - q.w) * s2);
#pragma unroll
        for (int r = 0; r < 8; r++){
            float v = fmaf(px[r], q.x, fmaf(py[r], q.y, fmaf(pz[r], q.z, tj)));
            m[r] = fmaxf(m[r], v);
        }
    }

    __shared__ float sred[8][8];
    __shared__ float sbro[8];
#pragma unroll
    for (int r = 0; r < 8; r++){
        float v = m[r];
#pragma unroll
        for (int o = 16; o; o >>= 1) v = fmaxf(v, __shfl_xor_sync(0xffffffffu, v, o));
        if ((tid & 31) == 0) sred[tid >> 5][r] = v;
    }
    __syncthreads();
    if (tid < 8){
        float v = sred[0][tid];
#pragma unroll
        for (int w = 1; w < 8; w++) v = fmaxf(v, sred[w][tid]);
        sbro[tid] = v;
    }
    __syncthreads();
    float M[8];
#pragma unroll
    for (int r = 0; r < 8; r++) M[r] = sbro[r];

    // ---- pass 2: sum of exp2(v - M) ----
    float s[8];
#pragma unroll
    for (int r = 0; r < 8; r++) s[r] = 0.0f;

    for (int j = tid; j < NPTS; j += 256){
        float4 q = Q[j];
        float tj = (mode == 0) ? (-q.w * s2) : ((dualin[j] - q.w) * s2);
#pragma unroll
        for (int r = 0; r < 8; r++){
            float v = fmaf(px[r], q.x, fmaf(py[r], q.y, fmaf(pz[r], q.z, tj)));
            s[r] += ex2f(v - M[r]);
        }
    }

#pragma unroll
    for (int r = 0; r < 8; r++){
        float v = s[r];
#pragma unroll
        for (int o = 16; o; o >>= 1) v += __shfl_xor_sync(0xffffffffu, v, o);
        if ((tid & 31) == 0) sred[tid >> 5][r] = v;
    }
    __syncthreads();
    if (tid < 8){
        float v = 0.0f;
#pragma unroll
        for (int w = 0; w < 8; w++) v += sred[w][tid];
        // re-derive this row's constant (avoid dynamic register-array index)
        float4 p  = P[row0 + tid];
        float rbv = LOGW_F * LOG2E_F - p.w * s2;   // (logw - 0.5|p|^2/eps)*log2e
        float res = -(eps * LN2_F) * (rbv + sbro[tid] + lg2f(v));
        int row = row0 + tid;
        if (mode == 1) res = 0.5f * (oldp[row] + res);
        outp[row] = res;
    }
}

// F = sum_b [ mean_i(b_x - a_x) + mean_j(a_y - b_y) ]
__global__ void finalize_kernel(int buf, float* __restrict__ out)
{
    const int tid = threadIdx.x;
    const float* ay = g_dual[buf][0];
    const float* bx = g_dual[buf][1];
    const float* ax = g_dual[buf][2];
    const float* by = g_dual[buf][3];
    double acc = 0.0;
    for (int i = tid; i < NTOT; i += 256){
        acc += (double)bx[i] - (double)ax[i];
        acc += (double)ay[i] - (double)by[i];
    }
    __shared__ double sd[8];
#pragma unroll
    for (int o = 16; o; o >>= 1) acc += __shfl_xor_sync(0xffffffffu, acc, o);
    if ((tid & 31) == 0) sd[tid >> 5] = acc;
    __syncthreads();
    if (tid == 0){
        double t = 0.0;
        for (int w = 0; w < 8; w++) t += sd[w];
        out[0] = (float)(t / 4096.0);
    }
}

extern "C" void kernel_launch(void* const* d_in, const int* in_sizes, int n_in,
                              void* d_out, int out_size)
{
    const float* x = (const float*)d_in[0];   // true_data
    const float* y = (const float*)d_in[1];   // particles
    float* out = (float*)d_out;

    pack_kernel<<<(NTOT + 255)/256, 256>>>(x, y);

    // geomloss eps schedule: [16] + exp(arange(2ln4, 2ln0.05, 2ln0.5)) + [0.0025]
    const float epsl[9] = {16.0f, 16.0f, 4.0f, 1.0f, 0.25f,
                           0.0625f, 0.015625f, 0.00390625f, 0.0025f};

    // init stage (eps = 16, no dual term) -> buffer 0
    softmin_kernel<<<4096, 256>>>(16.0f, 0, 0, 0);
    int cur = 0;
    // 9 symmetrized eps-scaling iterations (averaged updates, double buffered)
    for (int i = 0; i < 9; i++){
        softmin_kernel<<<4096, 256>>>(epsl[i], cur, cur ^ 1, 1);
        cur ^= 1;
    }
    // final extrapolation at eps = blur^2
    softmin_kernel<<<4096, 256>>>(0.0025f, cur, cur ^ 1, 2);
    cur ^= 1;

    finalize_kernel<<<1, 256>>>(cur, out);
}